// round 2
// baseline (speedup 1.0000x reference)
#include <cuda_runtime.h>
#include <cstdint>

#define MAX_NODES 100000
#define D 128

// Scratch: per-node projections s = x . w_s, d = x . w_d
__device__ float g_s[MAX_NODES];
__device__ float g_d[MAX_NODES];
// 1 if the index buffers are int64, 0 if int32
__device__ int g_idx64;

// Detect index dtype: for int64 nonneg indices < 2^31, every odd 32-bit word
// is 0. For int32 random indices in [0, 1e5), 64 odd words are ~never all 0.
__global__ void detect_idx_dtype_kernel(const unsigned int* __restrict__ src_words) {
    unsigned int acc = 0;
    #pragma unroll
    for (int i = 1; i < 128; i += 2) acc |= src_words[i];
    g_idx64 = (acc == 0) ? 1 : 0;
}

// Kernel 1: one warp per node. Each lane handles 4 contiguous floats (float4),
// two dot products reduced via warp shuffles.
__global__ void node_dots_kernel(const float* __restrict__ x,
                                 const float* __restrict__ W,
                                 int n_nodes) {
    __shared__ float ws[D];
    __shared__ float wd[D];
    int tid = threadIdx.x;
    for (int i = tid; i < D; i += blockDim.x) {
        ws[i] = W[i];
        wd[i] = W[D + i];
    }
    __syncthreads();

    int gwarp = (blockIdx.x * blockDim.x + tid) >> 5;
    int lane  = tid & 31;
    if (gwarp >= n_nodes) return;

    const float4* xr = reinterpret_cast<const float4*>(x + (size_t)gwarp * D);
    float4 v = xr[lane];
    float4 a = reinterpret_cast<const float4*>(ws)[lane];
    float4 c = reinterpret_cast<const float4*>(wd)[lane];

    float ssum = v.x * a.x + v.y * a.y + v.z * a.z + v.w * a.w;
    float dsum = v.x * c.x + v.y * c.y + v.z * c.z + v.w * c.w;

    #pragma unroll
    for (int off = 16; off > 0; off >>= 1) {
        ssum += __shfl_down_sync(0xFFFFFFFFu, ssum, off);
        dsum += __shfl_down_sync(0xFFFFFFFFu, dsum, off);
    }
    if (lane == 0) {
        g_s[gwarp] = ssum;
        g_d[gwarp] = dsum;
    }
}

// Kernel 2: one thread per edge. Scalar gathers into the 400KB L2-resident
// projection tables, fused sigmoid. Index dtype chosen by g_idx64 flag
// (uniform branch across the grid).
__global__ void edge_score_kernel(const void* __restrict__ src,
                                  const void* __restrict__ dst,
                                  const float* __restrict__ b,
                                  float* __restrict__ out,
                                  int n_edges) {
    int e = blockIdx.x * blockDim.x + threadIdx.x;
    if (e >= n_edges) return;
    int si, di;
    if (g_idx64) {
        si = (int)((const long long*)src)[e];
        di = (int)((const long long*)dst)[e];
    } else {
        si = ((const int*)src)[e];
        di = ((const int*)dst)[e];
    }
    float logit = g_s[si] + g_d[di] + __ldg(b);
    out[e] = 1.0f / (1.0f + __expf(-logit));
}

extern "C" void kernel_launch(void* const* d_in, const int* in_sizes, int n_in,
                              void* d_out, int out_size) {
    const float* x   = (const float*)d_in[0];
    const void*  src = d_in[1];
    const void*  dst = d_in[2];
    const float* W   = (const float*)d_in[3];
    const float* b   = (const float*)d_in[4];
    float*       out = (float*)d_out;

    int n_nodes = in_sizes[0] / D;
    int n_edges = in_sizes[1];

    detect_idx_dtype_kernel<<<1, 1>>>((const unsigned int*)src);

    // Kernel 1: 1 warp per node, 256 threads/block = 8 warps/block
    {
        int warps_per_block = 256 / 32;
        int blocks = (n_nodes + warps_per_block - 1) / warps_per_block;
        node_dots_kernel<<<blocks, 256>>>(x, W, n_nodes);
    }
    // Kernel 2: 1 thread per edge
    {
        int threads = 256;
        int blocks = (n_edges + threads - 1) / threads;
        edge_score_kernel<<<blocks, threads>>>(src, dst, b, out, n_edges);
    }
}

// round 3
// speedup vs baseline: 1.0755x; 1.0755x over previous
#include <cuda_runtime.h>
#include <cstdint>

#define MAX_NODES 100000
#define D 128

// Scratch: per-node projections s = x . w_s, d = x . w_d
__device__ float g_s[MAX_NODES];
__device__ float g_d[MAX_NODES];

// Kernel 1: one warp per node. Each lane handles 4 contiguous floats (float4),
// two dot products reduced via warp shuffles.
__global__ void node_dots_kernel(const float* __restrict__ x,
                                 const float* __restrict__ W,
                                 int n_nodes) {
    __shared__ float ws[D];
    __shared__ float wd[D];
    int tid = threadIdx.x;
    for (int i = tid; i < D; i += blockDim.x) {
        ws[i] = W[i];
        wd[i] = W[D + i];
    }
    __syncthreads();

    int gwarp = (blockIdx.x * blockDim.x + tid) >> 5;
    int lane  = tid & 31;
    if (gwarp >= n_nodes) return;

    const float4* xr = reinterpret_cast<const float4*>(x + (size_t)gwarp * D);
    float4 v = xr[lane];
    float4 a = reinterpret_cast<const float4*>(ws)[lane];
    float4 c = reinterpret_cast<const float4*>(wd)[lane];

    float ssum = v.x * a.x + v.y * a.y + v.z * a.z + v.w * a.w;
    float dsum = v.x * c.x + v.y * c.y + v.z * c.z + v.w * c.w;

    #pragma unroll
    for (int off = 16; off > 0; off >>= 1) {
        ssum += __shfl_down_sync(0xFFFFFFFFu, ssum, off);
        dsum += __shfl_down_sync(0xFFFFFFFFu, dsum, off);
    }
    if (lane == 0) {
        g_s[gwarp] = ssum;
        g_d[gwarp] = dsum;
    }
}

// Kernel 2: 4 edges per thread. int4 vector loads of indices (int32),
// 8 independent 4B gathers in flight (MLP=8), float4 store, fused sigmoid.
__global__ void edge_score4_kernel(const int4* __restrict__ src4,
                                   const int4* __restrict__ dst4,
                                   const float* __restrict__ b,
                                   float4* __restrict__ out4,
                                   int n_quads) {
    int q = blockIdx.x * blockDim.x + threadIdx.x;
    if (q >= n_quads) return;

    int4 s = src4[q];
    int4 d = dst4[q];
    float bias = __ldg(b);

    // Issue all 8 gathers before any dependent math (compiler will batch LDGs)
    float s0 = g_s[s.x], s1 = g_s[s.y], s2 = g_s[s.z], s3 = g_s[s.w];
    float d0 = g_d[d.x], d1 = g_d[d.y], d2 = g_d[d.z], d3 = g_d[d.w];

    float4 o;
    o.x = 1.0f / (1.0f + __expf(-(s0 + d0 + bias)));
    o.y = 1.0f / (1.0f + __expf(-(s1 + d1 + bias)));
    o.z = 1.0f / (1.0f + __expf(-(s2 + d2 + bias)));
    o.w = 1.0f / (1.0f + __expf(-(s3 + d3 + bias)));
    out4[q] = o;
}

// Tail kernel for n_edges % 4 != 0 (not hit for 1e6 edges, but keep correct)
__global__ void edge_score_tail_kernel(const int* __restrict__ src,
                                       const int* __restrict__ dst,
                                       const float* __restrict__ b,
                                       float* __restrict__ out,
                                       int start, int n_edges) {
    int e = start + blockIdx.x * blockDim.x + threadIdx.x;
    if (e >= n_edges) return;
    float logit = g_s[src[e]] + g_d[dst[e]] + __ldg(b);
    out[e] = 1.0f / (1.0f + __expf(-logit));
}

extern "C" void kernel_launch(void* const* d_in, const int* in_sizes, int n_in,
                              void* d_out, int out_size) {
    const float* x   = (const float*)d_in[0];
    const int*   src = (const int*)d_in[1];
    const int*   dst = (const int*)d_in[2];
    const float* W   = (const float*)d_in[3];
    const float* b   = (const float*)d_in[4];
    float*       out = (float*)d_out;

    int n_nodes = in_sizes[0] / D;
    int n_edges = in_sizes[1];

    // Kernel 1: 1 warp per node, 256 threads/block = 8 warps/block
    {
        int warps_per_block = 256 / 32;
        int blocks = (n_nodes + warps_per_block - 1) / warps_per_block;
        node_dots_kernel<<<blocks, 256>>>(x, W, n_nodes);
    }
    // Kernel 2: 4 edges per thread
    {
        int n_quads = n_edges / 4;
        int threads = 256;
        int blocks = (n_quads + threads - 1) / threads;
        if (blocks > 0)
            edge_score4_kernel<<<blocks, threads>>>((const int4*)src, (const int4*)dst,
                                                    b, (float4*)out, n_quads);
        int tail_start = n_quads * 4;
        int tail = n_edges - tail_start;
        if (tail > 0)
            edge_score_tail_kernel<<<1, 32>>>(src, dst, b, out, tail_start, n_edges);
    }
}

// round 4
// speedup vs baseline: 1.2555x; 1.1674x over previous
#include <cuda_runtime.h>
#include <cstdint>

#define MAX_NODES 100000
#define D 128

// Scratch: per-node projections s = x . w_s, d = x . w_d
__device__ float g_s[MAX_NODES];
__device__ float g_d[MAX_NODES];

// Kernel 1: 4 nodes per warp, all loads issued up-front for MLP=4.
// Each lane holds one float4 (16B) of each of the 4 node rows (contiguous
// 512B per row -> perfectly coalesced LDG.128). Two dot products per node
// reduced via warp shuffles (hidden behind memory latency).
__global__ void node_dots_kernel(const float4* __restrict__ x4,
                                 const float* __restrict__ W,
                                 int n_nodes) {
    __shared__ float4 ws4[32];
    __shared__ float4 wd4[32];
    int tid = threadIdx.x;
    if (tid < 32) ws4[tid] = ((const float4*)W)[tid];
    else if (tid < 64) wd4[tid - 32] = ((const float4*)W)[tid - 32 + 32];
    __syncthreads();

    int lane = tid & 31;
    int gwarp = (blockIdx.x * blockDim.x + tid) >> 5;
    int base = gwarp * 4;
    if (base >= n_nodes) return;

    float4 a = ws4[lane];
    float4 c = wd4[lane];

    // Up-front loads: 4 independent LDG.128 in flight per lane's slot
    int n1 = base + 1, n2 = base + 2, n3 = base + 3;
    bool h1 = n1 < n_nodes, h2 = n2 < n_nodes, h3 = n3 < n_nodes;
    float4 v0 = x4[(size_t)base * 32 + lane];
    float4 v1 = h1 ? x4[(size_t)n1 * 32 + lane] : make_float4(0.f, 0.f, 0.f, 0.f);
    float4 v2 = h2 ? x4[(size_t)n2 * 32 + lane] : make_float4(0.f, 0.f, 0.f, 0.f);
    float4 v3 = h3 ? x4[(size_t)n3 * 32 + lane] : make_float4(0.f, 0.f, 0.f, 0.f);

    float s0 = v0.x * a.x + v0.y * a.y + v0.z * a.z + v0.w * a.w;
    float d0 = v0.x * c.x + v0.y * c.y + v0.z * c.z + v0.w * c.w;
    float s1 = v1.x * a.x + v1.y * a.y + v1.z * a.z + v1.w * a.w;
    float d1 = v1.x * c.x + v1.y * c.y + v1.z * c.z + v1.w * c.w;
    float s2 = v2.x * a.x + v2.y * a.y + v2.z * a.z + v2.w * a.w;
    float d2 = v2.x * c.x + v2.y * c.y + v2.z * c.z + v2.w * c.w;
    float s3 = v3.x * a.x + v3.y * a.y + v3.z * a.z + v3.w * a.w;
    float d3 = v3.x * c.x + v3.y * c.y + v3.z * c.z + v3.w * c.w;

    #pragma unroll
    for (int off = 16; off > 0; off >>= 1) {
        s0 += __shfl_down_sync(0xFFFFFFFFu, s0, off);
        d0 += __shfl_down_sync(0xFFFFFFFFu, d0, off);
        s1 += __shfl_down_sync(0xFFFFFFFFu, s1, off);
        d1 += __shfl_down_sync(0xFFFFFFFFu, d1, off);
        s2 += __shfl_down_sync(0xFFFFFFFFu, s2, off);
        d2 += __shfl_down_sync(0xFFFFFFFFu, d2, off);
        s3 += __shfl_down_sync(0xFFFFFFFFu, s3, off);
        d3 += __shfl_down_sync(0xFFFFFFFFu, d3, off);
    }
    if (lane == 0) {
        g_s[base] = s0;
        g_d[base] = d0;
        if (h1) { g_s[n1] = s1; g_d[n1] = d1; }
        if (h2) { g_s[n2] = s2; g_d[n2] = d2; }
        if (h3) { g_s[n3] = s3; g_d[n3] = d3; }
    }
}

// Kernel 2: 4 edges per thread, 128-thread blocks for higher blocks/SM.
// int4 index loads, 8 independent 4B gathers in flight, float4 store.
__global__ void edge_score4_kernel(const int4* __restrict__ src4,
                                   const int4* __restrict__ dst4,
                                   const float* __restrict__ b,
                                   float4* __restrict__ out4,
                                   int n_quads) {
    int q = blockIdx.x * blockDim.x + threadIdx.x;
    if (q >= n_quads) return;

    int4 s = src4[q];
    int4 d = dst4[q];
    float bias = __ldg(b);

    float s0 = g_s[s.x], s1 = g_s[s.y], s2 = g_s[s.z], s3 = g_s[s.w];
    float d0 = g_d[d.x], d1 = g_d[d.y], d2 = g_d[d.z], d3 = g_d[d.w];

    float4 o;
    o.x = 1.0f / (1.0f + __expf(-(s0 + d0 + bias)));
    o.y = 1.0f / (1.0f + __expf(-(s1 + d1 + bias)));
    o.z = 1.0f / (1.0f + __expf(-(s2 + d2 + bias)));
    o.w = 1.0f / (1.0f + __expf(-(s3 + d3 + bias)));
    out4[q] = o;
}

// Tail kernel for n_edges % 4 != 0 (not hit for 1e6 edges, but keep correct)
__global__ void edge_score_tail_kernel(const int* __restrict__ src,
                                       const int* __restrict__ dst,
                                       const float* __restrict__ b,
                                       float* __restrict__ out,
                                       int start, int n_edges) {
    int e = start + blockIdx.x * blockDim.x + threadIdx.x;
    if (e >= n_edges) return;
    float logit = g_s[src[e]] + g_d[dst[e]] + __ldg(b);
    out[e] = 1.0f / (1.0f + __expf(-logit));
}

extern "C" void kernel_launch(void* const* d_in, const int* in_sizes, int n_in,
                              void* d_out, int out_size) {
    const float* x   = (const float*)d_in[0];
    const int*   src = (const int*)d_in[1];
    const int*   dst = (const int*)d_in[2];
    const float* W   = (const float*)d_in[3];
    const float* b   = (const float*)d_in[4];
    float*       out = (float*)d_out;

    int n_nodes = in_sizes[0] / D;
    int n_edges = in_sizes[1];

    // Kernel 1: 4 nodes per warp, 8 warps/block -> 32 nodes/block
    {
        int nodes_per_block = 8 * 4;
        int blocks = (n_nodes + nodes_per_block - 1) / nodes_per_block;
        node_dots_kernel<<<blocks, 256>>>((const float4*)x, W, n_nodes);
    }
    // Kernel 2: 4 edges per thread, 128-thread blocks
    {
        int n_quads = n_edges / 4;
        int threads = 128;
        int blocks = (n_quads + threads - 1) / threads;
        if (blocks > 0)
            edge_score4_kernel<<<blocks, threads>>>((const int4*)src, (const int4*)dst,
                                                    b, (float4*)out, n_quads);
        int tail_start = n_quads * 4;
        int tail = n_edges - tail_start;
        if (tail > 0)
            edge_score_tail_kernel<<<1, 32>>>(src, dst, b, out, tail_start, n_edges);
    }
}